// round 10
// baseline (speedup 1.0000x reference)
#include <cuda_runtime.h>
#include <cuda_bf16.h>
#include <cstdint>

#define BB      4
#define IN_DIM  8
#define OUT_DIM 64
#define N_WIN   64
#define N_SEQ   4096
#define N_REAL  6144

#define T_TILE  32
#define NTILES  (N_REAL / T_TILE)   // 192
#define THREADS 256

// Precomputed B fragments: one uint4 per (i, kc, c-n8group, lane) =
// {bh_q0, bh_q1, bl_q0, bl_q1} exact per-lane mma.sync register values. 128KB.
__device__ __align__(16) uint4 g_Bf[IN_DIM * 4 * 8 * 32];

// ---------------- helpers ----------------

// pack {lo16: bf16(z0), hi16: bf16(z1)}
__device__ __forceinline__ uint32_t bfpair(float z0, float z1) {
    uint32_t r;
    asm("cvt.rn.bf16x2.f32 %0, %1, %2;" : "=r"(r) : "f"(z1), "f"(z0));
    return r;
}

__device__ __forceinline__ void mma_bf16(float* d, const uint32_t* a, uint32_t b0, uint32_t b1) {
    asm volatile(
        "mma.sync.aligned.m16n8k16.row.col.f32.bf16.bf16.f32 "
        "{%0,%1,%2,%3}, {%4,%5,%6,%7}, {%8,%9}, {%0,%1,%2,%3};"
        : "+f"(d[0]), "+f"(d[1]), "+f"(d[2]), "+f"(d[3])
        : "r"(a[0]), "r"(a[1]), "r"(a[2]), "r"(a[3]), "r"(b0), "r"(b1));
}

// ---------------- weight prep ----------------
// B per i: B[k][o] = W[o][i][63-k].  m16n8k16 col-B fragment, n8 group c:
//   word q of lane l = ( B[kk][8c + l/4], B[kk+1][8c + l/4] ), kk = 16kc + 2(l%4) + 8q.

__global__ void wprep_frag(const float* __restrict__ w) {
    int g = blockIdx.x * 256 + threadIdx.x;     // 8192 = i*4kc*8c*32lane
    if (g >= IN_DIM * 4 * 8 * 32) return;
    int lane = g & 31;
    int c    = (g >> 5) & 7;
    int kc   = (g >> 8) & 3;
    int i    = (g >> 10) & 7;
    int o    = 8 * c + (lane >> 2);
    int kk   = 16 * kc + 2 * (lane & 3);
    const float* wr = w + (o * IN_DIM + i) * N_WIN;
    float v00 = wr[63 - kk],       v01 = wr[62 - kk];        // q=0
    float v10 = wr[63 - (kk + 8)], v11 = wr[62 - (kk + 8)];  // q=1
    __nv_bfloat16 h00 = __float2bfloat16(v00), h01 = __float2bfloat16(v01);
    __nv_bfloat16 h10 = __float2bfloat16(v10), h11 = __float2bfloat16(v11);
    uint4 r;
    r.x = bfpair(__bfloat162float(h00), __bfloat162float(h01));
    r.y = bfpair(__bfloat162float(h10), __bfloat162float(h11));
    r.z = bfpair(v00 - __bfloat162float(h00), v01 - __bfloat162float(h01));
    r.w = bfpair(v10 - __bfloat162float(h10), v11 - __bfloat162float(h11));
    g_Bf[g] = r;
}

// ---------------- main kernel ----------------
// SMEM: zpair_hi 8x128 u32 @0 | zpair_lo @4096 | zraw 8x128 f32 @8192 |
//       bias @12288 | outtile 64x36 f32 @12544
#define SM_ZPH  0
#define SM_ZPL  4096
#define SM_ZRAW 8192
#define SM_BIAS 12288
#define SM_OUT  12544
#define PITCHW  36
#define SMEM_TOTAL (SM_OUT + OUT_DIM * PITCHW * 4)   // 21760

__global__ __launch_bounds__(THREADS, 5)
void conv_mma(const float* __restrict__ x, const int* __restrict__ srcIdx,
              const float* __restrict__ bias, float* __restrict__ out) {
    extern __shared__ __align__(16) unsigned char smem[];
    uint32_t* zph_all = (uint32_t*)(smem + SM_ZPH);
    uint32_t* zpl_all = (uint32_t*)(smem + SM_ZPL);
    float*    zraw    = (float*)(smem + SM_ZRAW);
    float*    bias_s  = (float*)(smem + SM_BIAS);
    float*    outtile = (float*)(smem + SM_OUT);

    const int tid  = threadIdx.x;
    const int wid  = tid >> 5;
    const int lane = tid & 31;
    const int b    = blockIdx.x / NTILES;
    const int t0   = (blockIdx.x % NTILES) * T_TILE;

    if (tid < OUT_DIM) bias_s[tid] = bias[tid];
#pragma unroll
    for (int p = 0; p < 4; p++) zraw[tid + p * THREADS] = 0.f;
    __syncthreads();

    // ---- stage z window [t0-63, t0+32] (96 entries) via PARALLEL scan of sourceIdx ----
    // Thread scans 16 consecutive entries with 4 coalesced int4 loads — no dependent chain.
    {
        const int tlo = t0 - 63;
        const int4* r4 = (const int4*)(srcIdx + b * N_SEQ) + tid * 4;
        const float* xb = x + b * IN_DIM * N_SEQ;
#pragma unroll
        for (int q = 0; q < 4; q++) {
            int4 v = r4[q];
            int s0 = tid * 16 + q * 4;
            int vv[4] = {v.x, v.y, v.z, v.w};
#pragma unroll
            for (int e = 0; e < 4; e++) {
                int tl = vv[e] - tlo;
                if ((unsigned)tl < 96u) {
                    int s = s0 + e;
#pragma unroll
                    for (int i = 0; i < IN_DIM; i++)
                        zraw[i * 128 + tl] = xb[i * N_SEQ + s];
                }
            }
        }
    }
    __syncthreads();

    // ---- build hi/lo pair tables: zpair[i][k] = pack(z[k], z[k+1]) ----
#pragma unroll
    for (int p = 0; p < 4; p++) {
        int e = tid + p * THREADS;                   // 0..1023
        int k = e & 127;                             // stride 128 -> mask exact
        float z0 = zraw[e];
        float z1 = (k < 127) ? zraw[e + 1] : 0.f;
        uint32_t hp = bfpair(z0, z1);
        float h0 = __uint_as_float(hp << 16);
        float h1 = __uint_as_float(hp & 0xffff0000u);
        zph_all[e] = hp;
        zpl_all[e] = bfpair(z0 - h0, z1 - h1);
    }
    __syncthreads();

    // ---- fragment geometry: warp = m16 tile (mb) x n16 quarter (nq) ----
    const int mb  = wid & 1;                         // t rows [16mb, 16mb+16)
    const int nq  = wid >> 1;                        // o in [16nq, 16nq+16)
    const int lg  = lane >> 2;
    const int lp4 = lane & 3;
    const int rA  = 16 * mb + lg;

    float acc[2][4];
#pragma unroll
    for (int c = 0; c < 2; c++)
#pragma unroll
        for (int q = 0; q < 4; q++) acc[c][q] = 0.f;

    // ---- main loop: barrier-free streaming ----
#pragma unroll 1
    for (int i = 0; i < IN_DIM; i++) {
        const uint32_t* zph = zph_all + i * 128;
        const uint32_t* zpl = zpl_all + i * 128;
        const uint4*    bfi = g_Bf + (i * 4) * 256 + 2 * nq * 32 + lane;
#pragma unroll
        for (int kc = 0; kc < 4; kc++) {
            const int cb = 16 * kc + 2 * lp4;
            // Hankel A: A[r][c]=zwin[r+c] -> (row+8) and (col+8) share a word
            uint32_t ah[4], al[4];
            uint32_t w0h = zph[rA + cb], w8h = zph[rA + cb + 8], w16h = zph[rA + cb + 16];
            uint32_t w0l = zpl[rA + cb], w8l = zpl[rA + cb + 8], w16l = zpl[rA + cb + 16];
            ah[0] = w0h; ah[1] = w8h; ah[2] = w8h; ah[3] = w16h;
            al[0] = w0l; al[1] = w8l; al[2] = w8l; al[3] = w16l;

            const uint4* bp = bfi + kc * 256;
            uint4 B0 = bp[0];                        // n8 group 2nq
            uint4 B1 = bp[32];                       // n8 group 2nq+1

            mma_bf16(acc[0], ah, B0.x, B0.y);        // zhi*whi
            mma_bf16(acc[1], ah, B1.x, B1.y);
            mma_bf16(acc[0], ah, B0.z, B0.w);        // zhi*wlo
            mma_bf16(acc[1], ah, B1.z, B1.w);
            mma_bf16(acc[0], al, B0.x, B0.y);        // zlo*whi
            mma_bf16(acc[1], al, B1.x, B1.y);
        }
    }

    // ---- epilogue: D[t][o] + bias -> outtile[o][t] ----
#pragma unroll
    for (int c = 0; c < 2; c++) {
        int o0 = 16 * nq + 8 * c + 2 * lp4;
        int tl0 = rA;
        outtile[o0 * PITCHW + tl0]           = acc[c][0] + bias_s[o0];
        outtile[(o0 + 1) * PITCHW + tl0]     = acc[c][1] + bias_s[o0 + 1];
        outtile[o0 * PITCHW + tl0 + 8]       = acc[c][2] + bias_s[o0];
        outtile[(o0 + 1) * PITCHW + tl0 + 8] = acc[c][3] + bias_s[o0 + 1];
    }
    __syncthreads();

    // ---- coalesced stores: 512 float4 quads, 2 per thread ----
#pragma unroll
    for (int r2 = 0; r2 < 2; r2++) {
        int u  = tid + r2 * THREADS;                 // 0..511
        int o  = u >> 3;
        int tq = u & 7;
        float4 v = *(float4*)(outtile + o * PITCHW + 4 * tq);
        *(float4*)(out + (b * OUT_DIM + o) * N_REAL + t0 + 4 * tq) = v;
    }
}

// ---------------- launch ----------------

extern "C" void kernel_launch(void* const* d_in, const int* in_sizes, int n_in,
                              void* d_out, int out_size) {
    const float* x      = (const float*)d_in[0];   // (4, 8, 4096)
    const float* weight = (const float*)d_in[1];   // (64, 8, 64)
    const float* bias   = (const float*)d_in[2];   // (64,)
    const int*   srcIdx = (const int*)d_in[3];     // (4, 4096)
    float*       out    = (float*)d_out;           // (4, 64, 6144)

    static bool attr_done = false;
    if (!attr_done) {
        cudaFuncSetAttribute(conv_mma, cudaFuncAttributeMaxDynamicSharedMemorySize, SMEM_TOTAL);
        attr_done = true;
    }

    wprep_frag<<<(IN_DIM * 4 * 8 * 32 + 255) / 256, 256>>>(weight);
    conv_mma<<<BB * NTILES, THREADS, SMEM_TOTAL>>>(x, srcIdx, bias, out);
}